// round 2
// baseline (speedup 1.0000x reference)
#include <cuda_runtime.h>
#include <math.h>

// ---------------------------------------------------------------------------
// Problem constants
// ---------------------------------------------------------------------------
#define N64   64
#define G     262144      // 64^3
#define NATOM 128
#define KG    6
#define AK    768         // NATOM*KG

// ---------------------------------------------------------------------------
// Device scratch (static globals: no allocation allowed)
// ---------------------------------------------------------------------------
__device__ float  g_Exw[AK * N64];   // aw * exp(bw*(x_i-Xa)^2)   [ak][64]
__device__ float  g_Ey [AK * N64];   // exp(bw*(y_i-Ya)^2)
__device__ float  g_Ez [AK * N64];   // exp(bw*(z_i-Za)^2)
__device__ float  g_r  [G];          // real work buffer (density / final real)
__device__ float2 g_A  [G];          // complex work buffer A
__device__ float2 g_B  [G];          // complex work buffer B
__device__ float2 g_W  [N64];        // forward twiddles W[j] = exp(-2*pi*i*j/64)
__device__ double g_sum, g_sumsq;

// ---------------------------------------------------------------------------
// Kernel 1: precompute separable Gaussian tables, twiddles, zero stats
//   grid: 192 x 256   (192*256 = 49152 = AK*64)
// ---------------------------------------------------------------------------
__global__ void k_pre(const float* __restrict__ X,
                      const float* __restrict__ aw,
                      const float* __restrict__ bw,
                      const float* __restrict__ rgf)
{
    int t = blockIdx.x * 256 + threadIdx.x;
    if (blockIdx.x == 0) {
        if (threadIdx.x == 0) { g_sum = 0.0; g_sumsq = 0.0; }
        if (threadIdx.x < N64) {
            float ang = -2.0f * 3.14159265358979323846f * (float)threadIdx.x / 64.0f;
            float s, c;
            __sincosf(ang, &s, &c);
            g_W[threadIdx.x] = make_float2(c, s);
        }
    }
    if (t < AK * N64) {
        int ak = t >> 6;
        int i  = t & 63;
        int a  = ak / KG;
        int k  = ak - a * KG;
        float b = bw[a * KG + k];
        float w = aw[a * KG + k];
        // axis coordinates straight from the provided real-space grid
        float cx = rgf[(size_t)i * 4096 * 3 + 0];
        float cy = rgf[(size_t)i * 64   * 3 + 1];
        float cz = rgf[(size_t)i        * 3 + 2];
        float dx = cx - X[a * 3 + 0];
        float dy = cy - X[a * 3 + 1];
        float dz = cz - X[a * 3 + 2];
        g_Exw[t] = w * __expf(b * dx * dx);
        g_Ey [t] =     __expf(b * dy * dy);
        g_Ez [t] =     __expf(b * dz * dz);
    }
}

// ---------------------------------------------------------------------------
// Kernel 2: density contraction  rho[x,y,z] = sum_ak A'[ak,x]*Ez[ak,z]
//           with A'[ak,x] = Exw[ak,x]*Ey[ak,y]  (y fixed per block)
//   grid: 128 blocks (2 x-halves * 64 y) x 256 threads
//   each thread: 2x * 4z microtile, 768 * 8 FMA
// ---------------------------------------------------------------------------
__global__ void k_splat()
{
    __shared__ __align__(16) float A_sh[16 * 32];
    __shared__ __align__(16) float E_sh[16 * 64];

    int tid = threadIdx.x;
    int xb  = blockIdx.x >> 6;     // 0..1
    int y   = blockIdx.x & 63;     // 0..63
    int tz  = tid & 15;            // z group: z = tz*4..tz*4+3
    int txh = tid >> 4;            // 0..15: x = xb*32 + txh*2 + {0,1}

    float a00 = 0.f, a01 = 0.f, a02 = 0.f, a03 = 0.f;
    float a10 = 0.f, a11 = 0.f, a12 = 0.f, a13 = 0.f;

    for (int ak0 = 0; ak0 < AK; ak0 += 16) {
        // stage A' = Exw * Ey[.,y]
        for (int i = tid; i < 512; i += 256) {
            int c  = i >> 5;
            int xi = i & 31;
            float ey = g_Ey[(ak0 + c) * 64 + y];
            A_sh[c * 32 + xi] = g_Exw[(ak0 + c) * 64 + xb * 32 + xi] * ey;
        }
        // stage Ez rows
        for (int i = tid; i < 1024; i += 256) {
            int c = i >> 6;
            int z = i & 63;
            E_sh[c * 64 + z] = g_Ez[(ak0 + c) * 64 + z];
        }
        __syncthreads();
        #pragma unroll
        for (int c = 0; c < 16; c++) {
            float2 a = *(const float2*)&A_sh[c * 32 + txh * 2];
            float4 p = *(const float4*)&E_sh[c * 64 + tz  * 4];
            a00 = fmaf(a.x, p.x, a00); a01 = fmaf(a.x, p.y, a01);
            a02 = fmaf(a.x, p.z, a02); a03 = fmaf(a.x, p.w, a03);
            a10 = fmaf(a.y, p.x, a10); a11 = fmaf(a.y, p.y, a11);
            a12 = fmaf(a.y, p.z, a12); a13 = fmaf(a.y, p.w, a13);
        }
        __syncthreads();
    }
    int x0   = xb * 32 + txh * 2;
    int base = x0 * 4096 + y * 64 + tz * 4;
    *(float4*)&g_r[base       ] = make_float4(a00, a01, a02, a03);
    *(float4*)&g_r[base + 4096] = make_float4(a10, a11, a12, a13);
}

// ---------------------------------------------------------------------------
// DFT passes. All fftshift/ifftshift pairs cancel analytically; the spectral
// step reduces to A = FFT3(rho); A *= Hs; out = IFFT3(A)/N^3 with
// Hs[k] = hamming[(k+32)&63] per axis. 64-point DFTs done directly from a
// 64-entry twiddle table.
// ---------------------------------------------------------------------------

// ---- z axis, forward, real input ------------------------------------------
// grid: 128 x 256. Block handles 32 contiguous lines (line = x*64+y).
__global__ void k_zfwd()
{
    __shared__ float  sh[64 * 33];
    __shared__ float2 Wsh[64];
    int tid = threadIdx.x;
    int p0  = blockIdx.x * 32;
    if (tid < 64) Wsh[tid] = g_W[tid];
    for (int i = tid; i < 2048; i += 256) {
        int line = i >> 6, n = i & 63;
        sh[n * 33 + line] = g_r[(p0 + line) * 64 + n];
    }
    __syncthreads();
    int line = tid & 31, kg = tid >> 5;
    float2 acc[8];
    #pragma unroll
    for (int kk = 0; kk < 8; kk++) acc[kk] = make_float2(0.f, 0.f);
    for (int n = 0; n < 64; n++) {
        float x = sh[n * 33 + line];
        #pragma unroll
        for (int kk = 0; kk < 8; kk++) {
            int k = kg * 8 + kk;
            float2 w = Wsh[(k * n) & 63];
            acc[kk].x = fmaf(x, w.x, acc[kk].x);
            acc[kk].y = fmaf(x, w.y, acc[kk].y);
        }
    }
    int base = (p0 + line) * 64;
    #pragma unroll
    for (int kk = 0; kk < 8; kk++) g_A[base + kg * 8 + kk] = acc[kk];
}

// ---- y axis, complex pass (forward or inverse) ----------------------------
// array viewed as [p=x(64)][n=y(64)][q=z(64)]; grid 128 x 256
template <bool INV>
__device__ __forceinline__ void dft_y(const float2* __restrict__ in,
                                      float2* __restrict__ out)
{
    __shared__ float2 sh[64 * 32];
    __shared__ float2 Wsh[64];
    int tid = threadIdx.x;
    int p   = blockIdx.x >> 1;
    int q0  = (blockIdx.x & 1) * 32;
    if (tid < 64) Wsh[tid] = g_W[tid];

    for (int i = tid; i < 2048; i += 256) {
        int n  = i >> 5;
        int qi = i & 31;
        sh[n * 32 + qi] = in[p * 4096 + n * 64 + q0 + qi];
    }
    __syncthreads();

    int q = tid & 31, kg = tid >> 5;
    float2 acc[8];
    #pragma unroll
    for (int kk = 0; kk < 8; kk++) acc[kk] = make_float2(0.f, 0.f);
    for (int n = 0; n < 64; n++) {
        float2 x = sh[n * 32 + q];
        #pragma unroll
        for (int kk = 0; kk < 8; kk++) {
            int k = kg * 8 + kk;
            int j = (k * n) & 63;
            if (INV) j = (64 - j) & 63;
            float2 w = Wsh[j];
            acc[kk].x = fmaf( x.x, w.x, acc[kk].x);
            acc[kk].x = fmaf(-x.y, w.y, acc[kk].x);
            acc[kk].y = fmaf( x.x, w.y, acc[kk].y);
            acc[kk].y = fmaf( x.y, w.x, acc[kk].y);
        }
    }
    #pragma unroll
    for (int kk = 0; kk < 8; kk++) {
        int k = kg * 8 + kk;
        out[p * 4096 + k * 64 + q0 + q] = acc[kk];
    }
}

__global__ void k_yfwd() { dft_y<false>(g_A, g_B); }
__global__ void k_yinv() { dft_y<true >(g_B, g_A); }

// ---- x axis: fused forward DFT -> Hamming -> inverse DFT, in place --------
// array viewed as [n=x(64)][q=y*64+z (4096)]; block owns a 32-wide q tile
// for ALL x, so the full x-spectrum lives in the block: one shared tile
// serves input, filtered spectrum, and inverse input. grid: 128 x 256.
__global__ void k_xboth(const float* __restrict__ ham)
{
    __shared__ float2 sh[64 * 32];
    __shared__ float2 Wsh[64];
    int tid = threadIdx.x;
    int q0  = blockIdx.x * 32;
    if (tid < 64) Wsh[tid] = g_W[tid];

    for (int i = tid; i < 2048; i += 256) {
        int n  = i >> 5;
        int qi = i & 31;
        sh[n * 32 + qi] = g_B[n * 4096 + q0 + qi];
    }
    __syncthreads();

    int q = tid & 31, kg = tid >> 5;
    int gq = q0 + q;
    int hy = ((gq >> 6) + 32) & 63;
    int hz = ((gq & 63) + 32) & 63;

    // forward x-DFT
    float2 acc[8];
    #pragma unroll
    for (int kk = 0; kk < 8; kk++) acc[kk] = make_float2(0.f, 0.f);
    for (int n = 0; n < 64; n++) {
        float2 x = sh[n * 32 + q];
        #pragma unroll
        for (int kk = 0; kk < 8; kk++) {
            int k = kg * 8 + kk;
            float2 w = Wsh[(k * n) & 63];
            acc[kk].x = fmaf( x.x, w.x, acc[kk].x);
            acc[kk].x = fmaf(-x.y, w.y, acc[kk].x);
            acc[kk].y = fmaf( x.x, w.y, acc[kk].y);
            acc[kk].y = fmaf( x.y, w.x, acc[kk].y);
        }
    }
    __syncthreads();   // all forward reads of sh complete

    // Hamming filter, write spectrum back into the same tile
    #pragma unroll
    for (int kk = 0; kk < 8; kk++) {
        int k  = kg * 8 + kk;
        int hx = (k + 32) & 63;
        float h = ham[(hx << 12) | (hy << 6) | hz];
        sh[k * 32 + q] = make_float2(acc[kk].x * h, acc[kk].y * h);
    }
    __syncthreads();

    // inverse x-DFT
    float2 acc2[8];
    #pragma unroll
    for (int kk = 0; kk < 8; kk++) acc2[kk] = make_float2(0.f, 0.f);
    for (int n = 0; n < 64; n++) {
        float2 x = sh[n * 32 + q];
        #pragma unroll
        for (int kk = 0; kk < 8; kk++) {
            int k = kg * 8 + kk;
            int j = (64 - ((k * n) & 63)) & 63;
            float2 w = Wsh[j];
            acc2[kk].x = fmaf( x.x, w.x, acc2[kk].x);
            acc2[kk].x = fmaf(-x.y, w.y, acc2[kk].x);
            acc2[kk].y = fmaf( x.x, w.y, acc2[kk].y);
            acc2[kk].y = fmaf( x.y, w.x, acc2[kk].y);
        }
    }
    #pragma unroll
    for (int kk = 0; kk < 8; kk++) {
        int k = kg * 8 + kk;
        g_B[k * 4096 + q0 + q] = acc2[kk];
    }
}

// ---- z axis, inverse, real output + fused sum/sumsq reduction -------------
__global__ void k_zinv()
{
    __shared__ float2 sh[64 * 33];
    __shared__ float2 Wsh[64];
    int tid = threadIdx.x;
    int p0  = blockIdx.x * 32;
    if (tid < 64) Wsh[tid] = g_W[tid];
    for (int i = tid; i < 2048; i += 256) {
        int line = i >> 6, n = i & 63;
        sh[n * 33 + line] = g_A[(p0 + line) * 64 + n];
    }
    __syncthreads();
    int line = tid & 31, kg = tid >> 5;
    float acc[8];
    #pragma unroll
    for (int kk = 0; kk < 8; kk++) acc[kk] = 0.f;
    for (int n = 0; n < 64; n++) {
        float2 x = sh[n * 33 + line];
        #pragma unroll
        for (int kk = 0; kk < 8; kk++) {
            int k = kg * 8 + kk;
            int j = (64 - ((k * n) & 63)) & 63;
            float2 w = Wsh[j];
            acc[kk] = fmaf( x.x, w.x, acc[kk]);
            acc[kk] = fmaf(-x.y, w.y, acc[kk]);
        }
    }
    const float scale = 1.0f / 262144.0f;   // combined ortho norm = 1/N^3
    int base = (p0 + line) * 64;
    double s1 = 0.0, s2 = 0.0;
    #pragma unroll
    for (int kk = 0; kk < 8; kk++) {
        float v = acc[kk] * scale;
        g_r[base + kg * 8 + kk] = v;
        double d = (double)v;
        s1 += d;
        s2 += d * d;
    }
    // warp + block reduction, one atomic pair per block
    #pragma unroll
    for (int o = 16; o > 0; o >>= 1) {
        s1 += __shfl_down_sync(0xFFFFFFFFu, s1, o);
        s2 += __shfl_down_sync(0xFFFFFFFFu, s2, o);
    }
    __shared__ double sm1[8], sm2[8];
    int lane = tid & 31, w = tid >> 5;
    if (lane == 0) { sm1[w] = s1; sm2[w] = s2; }
    __syncthreads();
    if (tid == 0) {
        double t1 = 0.0, t2 = 0.0;
        #pragma unroll
        for (int i = 0; i < 8; i++) { t1 += sm1[i]; t2 += sm2[i]; }
        atomicAdd(&g_sum,   t1);
        atomicAdd(&g_sumsq, t2);
    }
}

// ---------------------------------------------------------------------------
// Normalize: out = (v - mean) / (std + 1e-8)
// ---------------------------------------------------------------------------
__global__ void k_norm(float* __restrict__ out)
{
    int i = blockIdx.x * 256 + threadIdx.x;
    double mean = g_sum / (double)G;
    double var  = g_sumsq / (double)G - mean * mean;
    double stdv = sqrt(var > 0.0 ? var : 0.0);
    float  inv  = (float)(1.0 / (stdv + 1e-8));
    float  m    = (float)mean;
    out[i] = (g_r[i] - m) * inv;
}

// ---------------------------------------------------------------------------
// Launch
//   inputs: 0=X(384) 1=aw(768) 2=bw(768) 3=real_grid_flat(786432) 4=hamming(262144)
// ---------------------------------------------------------------------------
extern "C" void kernel_launch(void* const* d_in, const int* in_sizes, int n_in,
                              void* d_out, int out_size)
{
    const float* X   = (const float*)d_in[0];
    const float* aw  = (const float*)d_in[1];
    const float* bw  = (const float*)d_in[2];
    const float* rgf = (const float*)d_in[3];
    const float* ham = (const float*)d_in[4];
    float* out = (float*)d_out;

    k_pre  <<<192, 256>>>(X, aw, bw, rgf);
    k_splat<<<128, 256>>>();
    k_zfwd <<<128, 256>>>();
    k_yfwd <<<128, 256>>>();
    k_xboth<<<128, 256>>>(ham);
    k_yinv <<<128, 256>>>();
    k_zinv <<<128, 256>>>();
    k_norm <<<1024, 256>>>(out);
}

// round 5
// speedup vs baseline: 2.9255x; 2.9255x over previous
#include <cuda_runtime.h>
#include <math.h>

// ---------------------------------------------------------------------------
// Problem constants
// ---------------------------------------------------------------------------
#define N64   64
#define G     262144      // 64^3
#define NATOM 128
#define KG    6
#define AK    768         // NATOM*KG
#define NS    33          // surviving frequencies per axis: s in [-16,16]

// ---------------------------------------------------------------------------
// Device scratch (static globals: no allocation allowed)
// ---------------------------------------------------------------------------
__device__ float2 g_Ft [3 * N64 * AK]; // per-axis table DFTs, [axis][k][ak]
__device__ float  g_r  [G];            // final real-space result
__device__ float2 g_A  [G];            // x-inverse output: [kzs][x(stride34)][kys]
__device__ float2 g_B  [G];            // y-inverse output: [kzs][y][x]
__device__ float2 g_W  [N64];          // twiddles W[j] = exp(-2*pi*i*j/64)
__device__ double g_sum, g_sumsq;

// ---------------------------------------------------------------------------
// Kernel 1 (fused): Gaussian table rows -> 64-pt DFT -> g_Ft (transposed).
//   Raw tables never touch global memory. Block = 4 rows of 2304 (3*768).
//   Ft[axis][k][ak] = sum_n t[ak][n] * W[(k*n)&63],
//   t = aw*exp(bw*dx^2) for axis 0, exp(bw*dy^2)/exp(bw*dz^2) for axes 1/2.
//   grid: 576 x 256
// ---------------------------------------------------------------------------
__global__ void k_tab(const float* __restrict__ X,
                      const float* __restrict__ aw,
                      const float* __restrict__ bw,
                      const float* __restrict__ rgf)
{
    __shared__ float  Rsh[4 * 64];
    __shared__ float2 Wsh[64];
    int tid  = threadIdx.x;
    int row0 = blockIdx.x * 4;

    if (tid < 64) {
        float ang = -2.0f * 3.14159265358979323846f * (float)tid / 64.0f;
        float s, c;
        __sincosf(ang, &s, &c);
        Wsh[tid] = make_float2(c, s);
        if (blockIdx.x == 0) g_W[tid] = Wsh[tid];
    }
    if (blockIdx.x == 0 && tid == 0) { g_sum = 0.0; g_sumsq = 0.0; }

    int r    = tid >> 6, n = tid & 63;
    int row  = row0 + r;
    int axis = row / 768;
    int ak   = row - axis * 768;
    int a    = ak / KG;
    int kk   = ak - a * KG;
    {
        float b  = bw[a * KG + kk];
        float wc = aw[a * KG + kk];
        float c  = (axis == 0) ? rgf[n * 12288]
                 : (axis == 1) ? rgf[n * 192 + 1]
                               : rgf[n * 3 + 2];
        float d  = c - X[a * 3 + axis];
        float v  = __expf(b * d * d);
        if (axis == 0) v *= wc;
        Rsh[r * 64 + n] = v;
    }
    __syncthreads();

    int k = n;   // DFT output index for this thread
    float2 acc = make_float2(0.f, 0.f);
    for (int m = 0; m < 64; m++) {
        float  x = Rsh[r * 64 + m];
        float2 w = Wsh[(k * m) & 63];
        acc.x = fmaf(x, w.x, acc.x);
        acc.y = fmaf(x, w.y, acc.y);
    }
    g_Ft[axis * (N64 * AK) + k * AK + ak] = acc;
}

// ---------------------------------------------------------------------------
// Kernel 2: spectrum on the Hamming ball + fused x-inverse.
//   For each (ky,kz) column (33x33 = 1089 of them, 8 per block):
//     P[ak]  = Fy[ak,ky]*Fz[ak,kz]
//     S[kx]  = ham * sum_ak Fx[ak,kx]*P[ak]        (33 kx)
//     A[x]   = sum_kx S[kx]*W^{+x*kx}              (x-inverse, 64 outputs)
//   ham==0 outside the ball, so annulus columns vanish automatically.
//   grid: 137 x 512. Warp pair per column (ak chunks split by parity).
// ---------------------------------------------------------------------------
__global__ void __launch_bounds__(512) k_spec(const float* __restrict__ ham)
{
    __shared__ float2 Fx_sh[NS * 129];   // [sxs][ak-chunk], stride 129 (pad)
    __shared__ float2 P_sh [8 * 128];    // [col][ak-chunk]
    __shared__ float2 Spart[16 * NS];    // per-warp partials, then filtered S
    __shared__ float2 Wsh  [64];
    __shared__ int    kyi_sh[8], kzi_sh[8];

    int tid = threadIdx.x;
    int c0  = blockIdx.x * 8;
    if (tid < 64) Wsh[tid] = g_W[tid];
    if (tid < 8) {
        int cg = c0 + tid; if (cg > 1088) cg = 1088;
        int kys = cg % NS, kzs = cg / NS;
        kyi_sh[tid] = (kys - 16) & 63;
        kzi_sh[tid] = (kzs - 16) & 63;
    }
    __syncthreads();

    int w = tid >> 5, lane = tid & 31;
    int colw = w >> 1, half = w & 1;
    float2 S  = make_float2(0.f, 0.f);   // kx slot = lane (sxs 0..31)
    float2 S2 = make_float2(0.f, 0.f);   // sxs = 32, lane-split partial

    for (int ch = 0; ch < 6; ch++) {
        int ak0 = ch * 128;
        for (int i = tid; i < NS * 128; i += 512) {
            int sxs = i >> 7, ak = i & 127;
            int kxi = (sxs - 16) & 63;
            Fx_sh[sxs * 129 + ak] = g_Ft[kxi * AK + ak0 + ak];
        }
        for (int i = tid; i < 8 * 128; i += 512) {
            int col = i >> 7, ak = i & 127;
            float2 a = g_Ft[N64 * AK     + kyi_sh[col] * AK + ak0 + ak];
            float2 b = g_Ft[2 * N64 * AK + kzi_sh[col] * AK + ak0 + ak];
            P_sh[i] = make_float2(a.x * b.x - a.y * b.y,
                                  a.x * b.y + a.y * b.x);
        }
        __syncthreads();
        if ((ch & 1) == half) {
            const float2* Pr = &P_sh[colw * 128];
            const float2* Fr = &Fx_sh[lane * 129];
            #pragma unroll 8
            for (int ak = 0; ak < 128; ak++) {
                float2 p = Pr[ak], f = Fr[ak];
                S.x = fmaf(p.x, f.x, S.x); S.x = fmaf(-p.y, f.y, S.x);
                S.y = fmaf(p.x, f.y, S.y); S.y = fmaf( p.y, f.x, S.y);
            }
            const float2* F32 = &Fx_sh[32 * 129];
            #pragma unroll
            for (int j = 0; j < 4; j++) {
                int ak = lane + j * 32;
                float2 p = Pr[ak], f = F32[ak];
                S2.x = fmaf(p.x, f.x, S2.x); S2.x = fmaf(-p.y, f.y, S2.x);
                S2.y = fmaf(p.x, f.y, S2.y); S2.y = fmaf( p.y, f.x, S2.y);
            }
        }
        __syncthreads();
    }
    // reduce the lane-split sxs=32 accumulator within the warp
    #pragma unroll
    for (int o = 16; o; o >>= 1) {
        S2.x += __shfl_xor_sync(0xFFFFFFFFu, S2.x, o);
        S2.y += __shfl_xor_sync(0xFFFFFFFFu, S2.y, o);
    }
    Spart[w * NS + lane] = S;
    if (lane == 0) Spart[w * NS + 32] = S2;
    __syncthreads();

    // combine warp-pair halves + Hamming
    float2 v = make_float2(0.f, 0.f);
    int colc = 0, sxsc = 0;
    if (tid < 8 * NS) {
        colc = tid / NS; sxsc = tid - colc * NS;
        float2 va = Spart[(colc * 2    ) * NS + sxsc];
        float2 vb = Spart[(colc * 2 + 1) * NS + sxsc];
        int cg = c0 + colc; if (cg > 1088) cg = 1088;
        int kys = cg % NS, kzs = cg / NS;
        int hx = (sxsc + 16) & 63, hy = (kys + 16) & 63, hz = (kzs + 16) & 63;
        float h = ham[(hx << 12) | (hy << 6) | hz];
        v = make_float2((va.x + vb.x) * h, (va.y + vb.y) * h);
    }
    __syncthreads();
    if (tid < 8 * NS) Spart[colc * NS + sxsc] = v;
    __syncthreads();

    // fused x-inverse: thread -> (col, x)
    {
        int col = tid >> 6, x = tid & 63;
        int cg  = c0 + col;
        float2 T = make_float2(0.f, 0.f);
        #pragma unroll
        for (int sxs = 0; sxs < NS; sxs++) {
            float2 s = Spart[col * NS + sxs];
            int j = (-(x * (sxs - 16))) & 63;
            float2 wv = Wsh[j];
            T.x = fmaf(s.x, wv.x, T.x); T.x = fmaf(-s.y, wv.y, T.x);
            T.y = fmaf(s.x, wv.y, T.y); T.y = fmaf( s.y, wv.x, T.y);
        }
        if (cg < 1089) {
            int kys = cg % NS, kzs = cg / NS;
            g_A[kzs * 2176 + x * 34 + kys] = T;
        }
    }
}

// ---------------------------------------------------------------------------
// Kernel 3: sparse y-inverse.  B[kzs][y][x] = sum_{kys} A[kzs][x][kys]*W^{+y*sy}
//   grid: 132 x 256  (33 kzs * 4 x-tiles of 16)
// ---------------------------------------------------------------------------
__global__ void k_yinv()
{
    __shared__ float2 A_sh[16 * NS];
    __shared__ float2 Wsh[64];
    int tid = threadIdx.x;
    int kzs = blockIdx.x >> 2;
    int xt  = (blockIdx.x & 3) * 16;
    if (tid < 64) Wsh[tid] = g_W[tid];
    for (int i = tid; i < 16 * NS; i += 256) {
        int xl = i / NS, kys = i - xl * NS;
        A_sh[i] = g_A[kzs * 2176 + (xt + xl) * 34 + kys];
    }
    __syncthreads();
    int xl = tid & 15, yg = tid >> 4;       // 16 y-groups of 4
    float2 a0 = make_float2(0,0), a1 = a0, a2 = a0, a3 = a0;
    int y0 = yg * 4;
    for (int kys = 0; kys < NS; kys++) {
        float2 a = A_sh[xl * NS + kys];
        int s = kys - 16;
        float2 w0 = Wsh[(-( y0      * s)) & 63];
        float2 w1 = Wsh[(-((y0 + 1) * s)) & 63];
        float2 w2 = Wsh[(-((y0 + 2) * s)) & 63];
        float2 w3 = Wsh[(-((y0 + 3) * s)) & 63];
        a0.x = fmaf(a.x,w0.x,a0.x); a0.x = fmaf(-a.y,w0.y,a0.x);
        a0.y = fmaf(a.x,w0.y,a0.y); a0.y = fmaf( a.y,w0.x,a0.y);
        a1.x = fmaf(a.x,w1.x,a1.x); a1.x = fmaf(-a.y,w1.y,a1.x);
        a1.y = fmaf(a.x,w1.y,a1.y); a1.y = fmaf( a.y,w1.x,a1.y);
        a2.x = fmaf(a.x,w2.x,a2.x); a2.x = fmaf(-a.y,w2.y,a2.x);
        a2.y = fmaf(a.x,w2.y,a2.y); a2.y = fmaf( a.y,w2.x,a2.y);
        a3.x = fmaf(a.x,w3.x,a3.x); a3.x = fmaf(-a.y,w3.y,a3.x);
        a3.y = fmaf(a.x,w3.y,a3.y); a3.y = fmaf( a.y,w3.x,a3.y);
    }
    int x = xt + xl;
    g_B[kzs * 4096 + (y0    ) * 64 + x] = a0;
    g_B[kzs * 4096 + (y0 + 1) * 64 + x] = a1;
    g_B[kzs * 4096 + (y0 + 2) * 64 + x] = a2;
    g_B[kzs * 4096 + (y0 + 3) * 64 + x] = a3;
}

// ---------------------------------------------------------------------------
// Kernel 4: sparse z-inverse (real output, 1/N^3 scale) + fused reduction
//   out[x][y][z] = Re sum_{kzs} B[kzs][y][x]*W^{+z*sz}
//   grid: 128 x 256  (64 y * 2 x-tiles of 32)
// ---------------------------------------------------------------------------
__global__ void k_zinv()
{
    __shared__ float2 Bsh[NS * 33];
    __shared__ float2 Wsh[64];
    int tid = threadIdx.x;
    int y   = blockIdx.x >> 1;
    int xt  = (blockIdx.x & 1) * 32;
    if (tid < 64) Wsh[tid] = g_W[tid];
    for (int i = tid; i < NS * 32; i += 256) {
        int kzs = i >> 5, xl = i & 31;
        Bsh[kzs * 33 + xl] = g_B[kzs * 4096 + y * 64 + xt + xl];
    }
    __syncthreads();
    int z = tid & 63, xg = tid >> 6;        // 4 x-groups of 8
    float acc[8];
    #pragma unroll
    for (int j = 0; j < 8; j++) acc[j] = 0.f;
    for (int kzs = 0; kzs < NS; kzs++) {
        int s = kzs - 16;
        float2 wv = Wsh[(-(z * s)) & 63];
        #pragma unroll
        for (int j = 0; j < 8; j++) {
            float2 b = Bsh[kzs * 33 + xg * 8 + j];
            acc[j] = fmaf(b.x, wv.x, acc[j]);
            acc[j] = fmaf(-b.y, wv.y, acc[j]);
        }
    }
    const float scale = 1.0f / 262144.0f;   // combined ortho norm = 1/N^3
    double s1 = 0.0, s2 = 0.0;
    #pragma unroll
    for (int j = 0; j < 8; j++) {
        float vv = acc[j] * scale;
        g_r[(xt + xg * 8 + j) * 4096 + y * 64 + z] = vv;
        double d = (double)vv;
        s1 += d; s2 += d * d;
    }
    #pragma unroll
    for (int o = 16; o > 0; o >>= 1) {
        s1 += __shfl_down_sync(0xFFFFFFFFu, s1, o);
        s2 += __shfl_down_sync(0xFFFFFFFFu, s2, o);
    }
    __shared__ double sm1[8], sm2[8];
    int lane = tid & 31, w = tid >> 5;
    if (lane == 0) { sm1[w] = s1; sm2[w] = s2; }
    __syncthreads();
    if (tid == 0) {
        double t1 = 0.0, t2 = 0.0;
        #pragma unroll
        for (int i = 0; i < 8; i++) { t1 += sm1[i]; t2 += sm2[i]; }
        atomicAdd(&g_sum,   t1);
        atomicAdd(&g_sumsq, t2);
    }
}

// ---------------------------------------------------------------------------
// Kernel 5: normalize  out = (v - mean) / (std + 1e-8)
// ---------------------------------------------------------------------------
__global__ void k_norm(float* __restrict__ out)
{
    int i = blockIdx.x * 256 + threadIdx.x;
    double mean = g_sum / (double)G;
    double var  = g_sumsq / (double)G - mean * mean;
    double stdv = sqrt(var > 0.0 ? var : 0.0);
    float  inv  = (float)(1.0 / (stdv + 1e-8));
    float  m    = (float)mean;
    out[i] = (g_r[i] - m) * inv;
}

// ---------------------------------------------------------------------------
// Launch
//   inputs: 0=X(384) 1=aw(768) 2=bw(768) 3=real_grid_flat(786432) 4=hamming(262144)
// ---------------------------------------------------------------------------
extern "C" void kernel_launch(void* const* d_in, const int* in_sizes, int n_in,
                              void* d_out, int out_size)
{
    const float* X   = (const float*)d_in[0];
    const float* aw  = (const float*)d_in[1];
    const float* bw  = (const float*)d_in[2];
    const float* rgf = (const float*)d_in[3];
    const float* ham = (const float*)d_in[4];
    float* out = (float*)d_out;

    k_tab  <<<576, 256>>>(X, aw, bw, rgf);
    k_spec <<<137, 512>>>(ham);
    k_yinv <<<132, 256>>>();
    k_zinv <<<128, 256>>>();
    k_norm <<<1024, 256>>>(out);
}

// round 6
// speedup vs baseline: 4.0000x; 1.3673x over previous
#include <cuda_runtime.h>
#include <math.h>

// ---------------------------------------------------------------------------
// Problem constants
// ---------------------------------------------------------------------------
#define N64   64
#define G     262144      // 64^3
#define NATOM 128
#define KG    6
#define AK    768         // NATOM*KG
#define NS    33          // surviving frequencies per axis: s in [-16,16]
#define NHALF 545         // half-spectrum columns: 16*33 + 17

// ---------------------------------------------------------------------------
// Device scratch (static globals: no allocation allowed)
// ---------------------------------------------------------------------------
__device__ float2 g_Ft [3 * N64 * AK]; // per-axis table DFTs, [axis][k][ak]
__device__ float  g_r  [G];            // final real-space result
__device__ float2 g_A  [NS * 64 * 34]; // x-inverse out: [kzs][x(stride34)][kys]
__device__ float2 g_W  [N64];          // twiddles W[j] = exp(-2*pi*i*j/64)
__device__ double g_sum, g_sumsq;

// ---------------------------------------------------------------------------
// Kernel 1 (fused): Gaussian table rows -> 64-pt DFT -> g_Ft (transposed).
//   Raw tables never touch global memory. Block = 4 rows of 2304 (3*768).
//   grid: 576 x 256
// ---------------------------------------------------------------------------
__global__ void k_tab(const float* __restrict__ X,
                      const float* __restrict__ aw,
                      const float* __restrict__ bw,
                      const float* __restrict__ rgf)
{
    __shared__ float  Rsh[4 * 64];
    __shared__ float2 Wsh[64];
    int tid  = threadIdx.x;
    int row0 = blockIdx.x * 4;

    if (tid < 64) {
        float ang = -2.0f * 3.14159265358979323846f * (float)tid / 64.0f;
        float s, c;
        __sincosf(ang, &s, &c);
        Wsh[tid] = make_float2(c, s);
        if (blockIdx.x == 0) g_W[tid] = Wsh[tid];
    }
    if (blockIdx.x == 0 && tid == 0) { g_sum = 0.0; g_sumsq = 0.0; }

    int r    = tid >> 6, n = tid & 63;
    int row  = row0 + r;
    int axis = row / 768;
    int ak   = row - axis * 768;
    int a    = ak / KG;
    int kk   = ak - a * KG;
    {
        float b  = bw[a * KG + kk];
        float wc = aw[a * KG + kk];
        float c  = (axis == 0) ? rgf[n * 12288]
                 : (axis == 1) ? rgf[n * 192 + 1]
                               : rgf[n * 3 + 2];
        float d  = c - X[a * 3 + axis];
        float v  = __expf(b * d * d);
        if (axis == 0) v *= wc;
        Rsh[r * 64 + n] = v;
    }
    __syncthreads();

    int k = n;   // DFT output index for this thread
    float2 acc = make_float2(0.f, 0.f);
    for (int m = 0; m < 64; m++) {
        float  x = Rsh[r * 64 + m];
        float2 w = Wsh[(k * m) & 63];
        acc.x = fmaf(x, w.x, acc.x);
        acc.y = fmaf(x, w.y, acc.y);
    }
    g_Ft[axis * (N64 * AK) + k * AK + ak] = acc;
}

// ---------------------------------------------------------------------------
// Kernel 2: half-spectrum (Hermitian) + Hamming + fused x-inverse.
//   545 (ky,kz) columns (kzs<16 all kys; kzs==16, kys<=16), 4 per block.
//   Per column: P[ak]=Fy*Fz; S[kx]=ham*sum_ak Fx[ak,kx]*P[ak] (33 kx);
//   A[x]=sum_kx S[kx]*W^{+x*kx}. Mirror column gets conj(A).
//   grid: 137 x 512. 4 warps per column, ak split in quarters of 32.
// ---------------------------------------------------------------------------
__global__ void __launch_bounds__(512) k_spec(const float* __restrict__ ham)
{
    __shared__ float2 Fx_sh[NS * 129];   // [sxs][ak-chunk], stride 129 (pad)
    __shared__ float2 P_sh [4 * 128];    // [col][ak-chunk]
    __shared__ float2 Spart[16 * NS];    // per-warp partials, then filtered S
    __shared__ float2 Wsh  [64];
    __shared__ int    kyi_sh[4], kzi_sh[4];

    int tid = threadIdx.x;
    int c0  = blockIdx.x * 4;
    if (tid < 64) Wsh[tid] = g_W[tid];
    if (tid < 4) {
        int cg = c0 + tid; if (cg > NHALF - 1) cg = NHALF - 1;
        int kzs = cg / NS, kys = cg - kzs * NS;
        kyi_sh[tid] = (kys - 16) & 63;
        kzi_sh[tid] = (kzs - 16) & 63;
    }
    __syncthreads();

    int w = tid >> 5, lane = tid & 31;
    int colw = w >> 2, q = w & 3;        // column-in-block, ak quarter
    float2 S  = make_float2(0.f, 0.f);   // kx slot = lane (sxs 0..31)
    float2 S2 = make_float2(0.f, 0.f);   // sxs = 32, lane-split partial

    for (int ch = 0; ch < 6; ch++) {
        int ak0 = ch * 128;
        for (int i = tid; i < NS * 128; i += 512) {
            int sxs = i >> 7, ak = i & 127;
            int kxi = (sxs - 16) & 63;
            Fx_sh[sxs * 129 + ak] = g_Ft[kxi * AK + ak0 + ak];
        }
        for (int i = tid; i < 4 * 128; i += 512) {
            int col = i >> 7, ak = i & 127;
            float2 a = g_Ft[N64 * AK     + kyi_sh[col] * AK + ak0 + ak];
            float2 b = g_Ft[2 * N64 * AK + kzi_sh[col] * AK + ak0 + ak];
            P_sh[i] = make_float2(a.x * b.x - a.y * b.y,
                                  a.x * b.y + a.y * b.x);
        }
        __syncthreads();
        {
            const float2* Pr = &P_sh[colw * 128 + q * 32];
            const float2* Fr = &Fx_sh[lane * 129 + q * 32];
            #pragma unroll 8
            for (int a = 0; a < 32; a++) {
                float2 p = Pr[a], f = Fr[a];
                S.x = fmaf(p.x, f.x, S.x); S.x = fmaf(-p.y, f.y, S.x);
                S.y = fmaf(p.x, f.y, S.y); S.y = fmaf( p.y, f.x, S.y);
            }
            // sxs = 32 slice, lane-parallel over this warp's quarter
            {
                float2 p = P_sh[colw * 128 + q * 32 + lane];
                float2 f = Fx_sh[32 * 129 + q * 32 + lane];
                S2.x = fmaf(p.x, f.x, S2.x); S2.x = fmaf(-p.y, f.y, S2.x);
                S2.y = fmaf(p.x, f.y, S2.y); S2.y = fmaf( p.y, f.x, S2.y);
            }
        }
        __syncthreads();
    }
    // reduce the lane-split sxs=32 accumulator within the warp
    #pragma unroll
    for (int o = 16; o; o >>= 1) {
        S2.x += __shfl_xor_sync(0xFFFFFFFFu, S2.x, o);
        S2.y += __shfl_xor_sync(0xFFFFFFFFu, S2.y, o);
    }
    Spart[w * NS + lane] = S;
    if (lane == 0) Spart[w * NS + 32] = S2;
    __syncthreads();

    // combine 4 warp partials per column + Hamming
    float2 v = make_float2(0.f, 0.f);
    int colc = 0, sxsc = 0;
    if (tid < 4 * NS) {
        colc = tid / NS; sxsc = tid - colc * NS;
        float2 acc = make_float2(0.f, 0.f);
        #pragma unroll
        for (int i = 0; i < 4; i++) {
            float2 t = Spart[(colc * 4 + i) * NS + sxsc];
            acc.x += t.x; acc.y += t.y;
        }
        int cg = c0 + colc; if (cg > NHALF - 1) cg = NHALF - 1;
        int kzs = cg / NS, kys = cg - kzs * NS;
        int hx = (sxsc + 16) & 63, hy = (kys + 16) & 63, hz = (kzs + 16) & 63;
        float h = ham[(hx << 12) | (hy << 6) | hz];
        v = make_float2(acc.x * h, acc.y * h);
    }
    __syncthreads();
    if (tid < 4 * NS) Spart[colc * NS + sxsc] = v;
    __syncthreads();

    // fused x-inverse (rotation twiddles) + Hermitian mirror write
    if (tid < 256) {
        int col = tid >> 6, x = tid & 63;
        int cg  = c0 + col; if (cg > NHALF - 1) cg = NHALF - 1;
        float2 T  = make_float2(0.f, 0.f);
        float2 wv = Wsh[(16 * x) & 63];      // s = -16 start
        float2 ws = Wsh[(-x) & 63];          // step: * e^{+2pi i x/64}
        #pragma unroll
        for (int sxs = 0; sxs < NS; sxs++) {
            float2 s = Spart[col * NS + sxs];
            T.x = fmaf(s.x, wv.x, T.x); T.x = fmaf(-s.y, wv.y, T.x);
            T.y = fmaf(s.x, wv.y, T.y); T.y = fmaf( s.y, wv.x, T.y);
            float2 nw = make_float2(wv.x * ws.x - wv.y * ws.y,
                                    wv.x * ws.y + wv.y * ws.x);
            wv = nw;
        }
        int kzs = cg / NS, kys = cg - kzs * NS;
        g_A[kzs * 2176 + x * 34 + kys] = T;
        g_A[(32 - kzs) * 2176 + x * 34 + (32 - kys)] = make_float2(T.x, -T.y);
    }
}

// ---------------------------------------------------------------------------
// Kernel 3: fused sparse y-inverse + z-inverse + reduction.
//   Block = (x, y-half of 32). Loads A[*,x,*] (33x33), y-inverts to C[kzs][yl],
//   z-inverts to 32x64 reals, writes g_r and accumulates sum/sumsq.
//   grid: 128 x 256
// ---------------------------------------------------------------------------
__global__ void k_yz()
{
    __shared__ float2 A_sh[NS * NS];     // [kzs][kys]
    __shared__ float2 C_sh[NS * 32];     // [kzs][yl]
    __shared__ float2 Wsh[64];
    int tid = threadIdx.x;
    int x   = blockIdx.x >> 1;
    int yh  = blockIdx.x & 1;
    if (tid < 64) Wsh[tid] = g_W[tid];
    for (int i = tid; i < NS * NS; i += 256) {
        int kzs = i / NS, kys = i - kzs * NS;
        A_sh[i] = g_A[kzs * 2176 + x * 34 + kys];
    }
    __syncthreads();

    // y-inverse: C[kzs][yl] = sum_kys A[kzs][kys] * e^{+2pi i y sy/64}
    for (int i = tid; i < NS * 32; i += 256) {
        int yl = i & 31, kzs = i >> 5;
        int y  = yh * 32 + yl;
        float2 acc = make_float2(0.f, 0.f);
        float2 wv  = Wsh[(16 * y) & 63];
        float2 ws  = Wsh[(-y) & 63];
        #pragma unroll
        for (int kys = 0; kys < NS; kys++) {
            float2 a = A_sh[kzs * NS + kys];
            acc.x = fmaf(a.x, wv.x, acc.x); acc.x = fmaf(-a.y, wv.y, acc.x);
            acc.y = fmaf(a.x, wv.y, acc.y); acc.y = fmaf( a.y, wv.x, acc.y);
            float2 nw = make_float2(wv.x * ws.x - wv.y * ws.y,
                                    wv.x * ws.y + wv.y * ws.x);
            wv = nw;
        }
        C_sh[kzs * 32 + yl] = acc;
    }
    __syncthreads();

    // z-inverse (real) + scale
    int z = tid & 63, yg = tid >> 6;     // 4 y-groups of 8
    float acc[8];
    #pragma unroll
    for (int j = 0; j < 8; j++) acc[j] = 0.f;
    float2 wv = Wsh[(16 * z) & 63];
    float2 ws = Wsh[(-z) & 63];
    for (int kzs = 0; kzs < NS; kzs++) {
        #pragma unroll
        for (int j = 0; j < 8; j++) {
            float2 c = C_sh[kzs * 32 + yg * 8 + j];
            acc[j] = fmaf(c.x, wv.x, acc[j]);
            acc[j] = fmaf(-c.y, wv.y, acc[j]);
        }
        float2 nw = make_float2(wv.x * ws.x - wv.y * ws.y,
                                wv.x * ws.y + wv.y * ws.x);
        wv = nw;
    }
    const float scale = 1.0f / 262144.0f;   // combined ortho norm = 1/N^3
    double s1 = 0.0, s2 = 0.0;
    #pragma unroll
    for (int j = 0; j < 8; j++) {
        float vv = acc[j] * scale;
        int y = yh * 32 + yg * 8 + j;
        g_r[x * 4096 + y * 64 + z] = vv;
        double d = (double)vv;
        s1 += d; s2 += d * d;
    }
    #pragma unroll
    for (int o = 16; o > 0; o >>= 1) {
        s1 += __shfl_down_sync(0xFFFFFFFFu, s1, o);
        s2 += __shfl_down_sync(0xFFFFFFFFu, s2, o);
    }
    __shared__ double sm1[8], sm2[8];
    int lane = tid & 31, w = tid >> 5;
    if (lane == 0) { sm1[w] = s1; sm2[w] = s2; }
    __syncthreads();
    if (tid == 0) {
        double t1 = 0.0, t2 = 0.0;
        #pragma unroll
        for (int i = 0; i < 8; i++) { t1 += sm1[i]; t2 += sm2[i]; }
        atomicAdd(&g_sum,   t1);
        atomicAdd(&g_sumsq, t2);
    }
}

// ---------------------------------------------------------------------------
// Kernel 4: normalize  out = (v - mean) / (std + 1e-8), float4 vectorized
//   grid: 256 x 256 (65536 float4)
// ---------------------------------------------------------------------------
__global__ void k_norm(float4* __restrict__ out)
{
    int i = blockIdx.x * 256 + threadIdx.x;
    double mean = g_sum / (double)G;
    double var  = g_sumsq / (double)G - mean * mean;
    double stdv = sqrt(var > 0.0 ? var : 0.0);
    float  inv  = (float)(1.0 / (stdv + 1e-8));
    float  m    = (float)mean;
    float4 v = ((const float4*)g_r)[i];
    out[i] = make_float4((v.x - m) * inv, (v.y - m) * inv,
                         (v.z - m) * inv, (v.w - m) * inv);
}

// ---------------------------------------------------------------------------
// Launch
//   inputs: 0=X(384) 1=aw(768) 2=bw(768) 3=real_grid_flat(786432) 4=hamming(262144)
// ---------------------------------------------------------------------------
extern "C" void kernel_launch(void* const* d_in, const int* in_sizes, int n_in,
                              void* d_out, int out_size)
{
    const float* X   = (const float*)d_in[0];
    const float* aw  = (const float*)d_in[1];
    const float* bw  = (const float*)d_in[2];
    const float* rgf = (const float*)d_in[3];
    const float* ham = (const float*)d_in[4];

    k_tab  <<<576, 256>>>(X, aw, bw, rgf);
    k_spec <<<137, 512>>>(ham);
    k_yz   <<<128, 256>>>();
    k_norm <<<256, 256>>>((float4*)d_out);
}